// round 10
// baseline (speedup 1.0000x reference)
#include <cuda_runtime.h>
#include <math.h>
#include <stdint.h>

// Problem dims (fixed by the dataset)
#define NR 4096           // bs*seq
#define KC 8192           // codebook size
#define DD 512            // feature dim
#define BSZ 8
#define TOT (NR * KC)

// ---------------- scratch (static __device__, allocation-free) ----------------
__device__ float g_logits[(size_t)NR * KC];   // 134 MB
__device__ float g_zz[NR];
__device__ float g_cc[KC];
__device__ float g_colsum[KC];
__device__ float g_scal[2];  // [0] = sum(p*logp), [1] = sum(diff^2)

// ---------------- zero accumulators (graph replays!) ----------------
__global__ void k_zero() {
    int i = blockIdx.x * blockDim.x + threadIdx.x;
    if (i < KC) g_colsum[i] = 0.f;
    if (i < 2)  g_scal[i]   = 0.f;
}

// ---------------- row squared norms ----------------
__global__ void k_sumsq(const float* __restrict__ Z, const float* __restrict__ CB) {
    int warp = (blockIdx.x * blockDim.x + threadIdx.x) >> 5;
    int lane = threadIdx.x & 31;
    if (warp >= NR + KC) return;
    const float* p = (warp < NR) ? (Z + (size_t)warp * DD)
                                 : (CB + (size_t)(warp - NR) * DD);
    float s = 0.f;
    #pragma unroll 4
    for (int i = lane; i < DD; i += 32) { float v = p[i]; s += v * v; }
    #pragma unroll
    for (int o = 16; o; o >>= 1) s += __shfl_xor_sync(0xffffffffu, s, o);
    if (lane == 0) { if (warp < NR) g_zz[warp] = s; else g_cc[warp - NR] = s; }
}

// ---------------- Threefry-2x32 gumbel (partitionable), pure fn of index ------
// counter (0, i), key (0, 42); 32-bit output = x0 ^ x1.
// uniform = bitcast(0x3f800000 | bits>>9) - 1
// gumbel = -log(-log(u+1e-10)+1e-10). Range: g in [-3.14, +15.95] exactly.
__device__ __forceinline__ float gumbel_of(unsigned i) {
    unsigned x0 = 0u, x1 = i;
    const unsigned k0 = 0u, k1 = 42u, k2 = 0x1BD11BDAu ^ k0 ^ k1;
    x0 += k0; x1 += k1;
#define TFR(r) { x0 += x1; x1 = __funnelshift_l(x1, x1, r); x1 ^= x0; }
    TFR(13) TFR(15) TFR(26) TFR(6)   x0 += k1; x1 += k2 + 1u;
    TFR(17) TFR(29) TFR(16) TFR(24)  x0 += k2; x1 += k0 + 2u;
    TFR(13) TFR(15) TFR(26) TFR(6)   x0 += k0; x1 += k1 + 3u;
    TFR(17) TFR(29) TFR(16) TFR(24)  x0 += k1; x1 += k2 + 4u;
    TFR(13) TFR(15) TFR(26) TFR(6)   x0 += k2; x1 += k0 + 5u;
#undef TFR
    unsigned bits = x0 ^ x1;
    float u = __uint_as_float(0x3f800000u | (bits >> 9)) - 1.0f;
    float x = u - 1.0f;                       // exact (Sterbenz) for u in [0.5,1]
    float pl = 1.f + x * (-0.5f + x * (0.33333334f + x * (-0.25f +
               x * (0.2f + x * (-0.16666667f + x * 0.14285715f)))));
    float ts = -x * pl;                       // accurate -ln(u), u near 1
    float tm = -__logf(u + 1e-10f);
    float t = (u > 0.9f) ? ts : tm;
    return -__logf(t + 1e-10f);
}

// ---------------- GEMM1: logits[n,k] = w*(2*Z.C^T - zz - cc) ----------------
// 128x128x16 CTA tile, 128 threads, 16x8 per-thread micro-tile, double-buffered.
// b-mapping tx*4 / 64+tx*4 -> conflict-free LDS wavefronts.
#define BK1 16
#define ALD 132   // 128 + 4 pad (row stride 528 B, 16B-aligned)
__global__ __launch_bounds__(128, 2) void k_gemm_logits(
    const float* __restrict__ Z, const float* __restrict__ CB,
    const float* __restrict__ varq) {
    __shared__ float As[2][BK1][ALD];
    __shared__ float Bs[2][BK1][ALD];
    const int tid = threadIdx.x;
    const int tx = tid & 15;          // n-group
    const int ty = tid >> 4;          // 0..7, m-group (16 rows each)
    const int rowBase = blockIdx.y * 128, colBase = blockIdx.x * 128;
    const int ar = tid >> 2;          // 0..31 loader row
    const int ac = tid & 3;           // k-offset/4

    const float* Ap = Z  + (size_t)(rowBase + ar) * DD + ac * 4;
    const float* Bp = CB + (size_t)(colBase + ar) * DD + ac * 4;

    float4 pa[4], pb[4];
    #pragma unroll
    for (int r = 0; r < 4; r++) {
        pa[r] = *(const float4*)(Ap + (size_t)(r * 32) * DD);
        pb[r] = *(const float4*)(Bp + (size_t)(r * 32) * DD);
    }
    #pragma unroll
    for (int r = 0; r < 4; r++) {
        As[0][ac*4+0][ar + r*32] = pa[r].x; As[0][ac*4+1][ar + r*32] = pa[r].y;
        As[0][ac*4+2][ar + r*32] = pa[r].z; As[0][ac*4+3][ar + r*32] = pa[r].w;
        Bs[0][ac*4+0][ar + r*32] = pb[r].x; Bs[0][ac*4+1][ar + r*32] = pb[r].y;
        Bs[0][ac*4+2][ar + r*32] = pb[r].z; Bs[0][ac*4+3][ar + r*32] = pb[r].w;
    }
    __syncthreads();

    float acc[16][8];
    #pragma unroll
    for (int i = 0; i < 16; i++)
        #pragma unroll
        for (int j = 0; j < 8; j++) acc[i][j] = 0.f;

    const int NIT = DD / BK1;   // 32
    for (int kk = 0; kk < NIT; kk++) {
        const int cur = kk & 1, nxt = cur ^ 1;
        if (kk + 1 < NIT) {
            const float* Ap2 = Ap + (kk + 1) * BK1;
            const float* Bp2 = Bp + (kk + 1) * BK1;
            #pragma unroll
            for (int r = 0; r < 4; r++) {
                pa[r] = *(const float4*)(Ap2 + (size_t)(r * 32) * DD);
                pb[r] = *(const float4*)(Bp2 + (size_t)(r * 32) * DD);
            }
        }
        #pragma unroll
        for (int p = 0; p < BK1; p++) {
            float a[16], b[8];
            *(float4*)(a)      = *(const float4*)&As[cur][p][ty * 16];
            *(float4*)(a + 4)  = *(const float4*)&As[cur][p][ty * 16 + 4];
            *(float4*)(a + 8)  = *(const float4*)&As[cur][p][ty * 16 + 8];
            *(float4*)(a + 12) = *(const float4*)&As[cur][p][ty * 16 + 12];
            *(float4*)(b)      = *(const float4*)&Bs[cur][p][tx * 4];
            *(float4*)(b + 4)  = *(const float4*)&Bs[cur][p][64 + tx * 4];
            #pragma unroll
            for (int i = 0; i < 16; i++)
                #pragma unroll
                for (int j = 0; j < 8; j++) acc[i][j] += a[i] * b[j];
        }
        if (kk + 1 < NIT) {
            #pragma unroll
            for (int r = 0; r < 4; r++) {
                As[nxt][ac*4+0][ar + r*32] = pa[r].x; As[nxt][ac*4+1][ar + r*32] = pa[r].y;
                As[nxt][ac*4+2][ar + r*32] = pa[r].z; As[nxt][ac*4+3][ar + r*32] = pa[r].w;
                Bs[nxt][ac*4+0][ar + r*32] = pb[r].x; Bs[nxt][ac*4+1][ar + r*32] = pb[r].y;
                Bs[nxt][ac*4+2][ar + r*32] = pb[r].z; Bs[nxt][ac*4+3][ar + r*32] = pb[r].w;
            }
        }
        __syncthreads();
    }

    const float w = 0.5f / fmaxf(varq[0], 1e-10f);
    float cc0[4], cc1[4];
    #pragma unroll
    for (int q = 0; q < 4; q++) {
        cc0[q] = g_cc[colBase + tx * 4 + q];
        cc1[q] = g_cc[colBase + 64 + tx * 4 + q];
    }
    #pragma unroll
    for (int i = 0; i < 16; i++) {
        int n = rowBase + ty * 16 + i;
        float zzn = g_zz[n];
        float* dst = g_logits + (size_t)n * KC + colBase;
        float4 v0, v1;
        v0.x = w * (2.f * acc[i][0] - zzn - cc0[0]);
        v0.y = w * (2.f * acc[i][1] - zzn - cc0[1]);
        v0.z = w * (2.f * acc[i][2] - zzn - cc0[2]);
        v0.w = w * (2.f * acc[i][3] - zzn - cc0[3]);
        v1.x = w * (2.f * acc[i][4] - zzn - cc1[0]);
        v1.y = w * (2.f * acc[i][5] - zzn - cc1[1]);
        v1.z = w * (2.f * acc[i][6] - zzn - cc1[2]);
        v1.w = w * (2.f * acc[i][7] - zzn - cc1[3]);
        *(float4*)(dst + tx * 4)      = v0;
        *(float4*)(dst + 64 + tx * 4) = v1;
    }
}

// ---------------- mega kernel: stats + colsum + sparse gumbel decode + diff ----
// Phase 1: (m1,Z1,T1) over logits only (exact kld_discrete).
// Phase 2: colsum atomics for p>1e-9; Threefry ONLY for l > m1-28.5 (provably
//          covers all y >= m2-18.8 since gumbel in [-3.14, 15.95]).
// Phase 3: m2/Z2 over candidates; z_dec = sum E_k*CB[k]; fused diff^2.
#define CCAP 256
__global__ __launch_bounds__(256) void k_mega(const float* __restrict__ Z,
                                              const float* __restrict__ CB,
                                              float* __restrict__ out) {
    const int n = blockIdx.x;
    const float* __restrict__ lrow = g_logits + (size_t)n * KC;
    const unsigned ibase = (unsigned)n * KC;
    const int t = threadIdx.x;

    float m1 = -1e30f, Z1 = 0.f, T1 = 0.f;
    for (int k = t * 4; k < KC; k += 1024) {
        float4 l4 = *(const float4*)(lrow + k);
        #pragma unroll
        for (int q = 0; q < 4; q++) {
            float l = (q == 0) ? l4.x : (q == 1) ? l4.y : (q == 2) ? l4.z : l4.w;
            if (l > m1) {
                float d = m1 - l;
                float sc = __expf(d);
                T1 = sc * (T1 + d * Z1);
                Z1 *= sc;
                m1 = l;
            }
            float e = __expf(l - m1);
            Z1 += e; T1 += e * (l - m1);
        }
    }
    __shared__ float sm[256], sz[256], st[256];
    __shared__ float s_fin[6];
    __shared__ int ccnt;
    __shared__ int   cidx[CCAP];
    __shared__ float cy[CCAP];
    sm[t] = m1; sz[t] = Z1; st[t] = T1;
    __syncthreads();
    for (int s = 128; s; s >>= 1) {
        if (t < s) {
            int o = t + s;
            float M = fmaxf(sm[t], sm[o]);
            float da = sm[t] - M, db = sm[o] - M;
            float ea = __expf(da), eb = __expf(db);
            st[t] = ea * (st[t] + da * sz[t]) + eb * (st[o] + db * sz[o]);
            sz[t] = ea * sz[t] + eb * sz[o];
            sm[t] = M;
        }
        __syncthreads();
    }
    if (t == 0) {
        float M = sm[0], Zz = sz[0], T = st[0];
        atomicAdd(&g_scal[0], T / Zz - logf(Zz));   // exact row sum p*logp
        s_fin[0] = M;
        s_fin[1] = 1.f / Zz;
        s_fin[2] = M + logf(Zz) - 20.723f;          // p > 1e-9 cut
        s_fin[3] = M - 28.5f;                       // candidate cut
        ccnt = 0;
    }
    __syncthreads();
    const float m1v = s_fin[0], iZ1 = s_fin[1], lpc = s_fin[2], ccut = s_fin[3];

    for (int k = t * 4; k < KC; k += 1024) {
        float4 l4 = *(const float4*)(lrow + k);
        #pragma unroll
        for (int q = 0; q < 4; q++) {
            float l = (q == 0) ? l4.x : (q == 1) ? l4.y : (q == 2) ? l4.z : l4.w;
            if (l > lpc)
                atomicAdd(&g_colsum[k + q], __expf(l - m1v) * iZ1);
            if (l > ccut) {
                int s = atomicAdd(&ccnt, 1);
                if (s < CCAP) {
                    cidx[s] = k + q;
                    cy[s]   = 2.0f * (l + gumbel_of(ibase + k + q));
                }
            }
        }
    }
    __syncthreads();
    const int cnt = min(ccnt, CCAP);

    // m2 = max over candidates
    float lm = -1e30f;
    for (int j = t; j < cnt; j += 256) lm = fmaxf(lm, cy[j]);
    sm[t] = lm;
    __syncthreads();
    for (int s = 128; s; s >>= 1) {
        if (t < s) sm[t] = fmaxf(sm[t], sm[t + s]);
        __syncthreads();
    }
    if (t == 0) s_fin[4] = sm[0];
    __syncthreads();
    const float m2v = s_fin[4];

    // Z2 over candidates
    float lz = 0.f;
    for (int j = t; j < cnt; j += 256) lz += __expf(cy[j] - m2v);
    sm[t] = lz;
    __syncthreads();
    for (int s = 128; s; s >>= 1) {
        if (t < s) sm[t] += sm[t + s];
        __syncthreads();
    }
    if (t == 0) s_fin[5] = 1.f / sm[0];
    __syncthreads();
    const float iZ2 = s_fin[5];
    for (int j = t; j < cnt; j += 256) cy[j] = __expf(cy[j] - m2v) * iZ2;
    __syncthreads();

    // decode: z_dec[n][:] = sum_j E_j * CB[cidx_j][:]; fused diff^2
    const int c0 = t * 2;
    float a0 = 0.f, a1 = 0.f;
    for (int j = 0; j < cnt; j++) {
        float e = cy[j];
        float2 cb = *(const float2*)(CB + (size_t)cidx[j] * DD + c0);
        a0 += e * cb.x;
        a1 += e * cb.y;
    }
    out[(size_t)n * DD + c0]     = a0;
    out[(size_t)n * DD + c0 + 1] = a1;
    float2 z2 = *(const float2*)(Z + (size_t)n * DD + c0);
    float d0 = z2.x - a0, d1 = z2.y - a1;
    sm[t] = d0 * d0 + d1 * d1;
    __syncthreads();
    for (int s = 128; s; s >>= 1) {
        if (t < s) sm[t] += sm[t + s];
        __syncthreads();
    }
    if (t == 0) atomicAdd(&g_scal[1], sm[0]);
}

// ---------------- finalize loss + perplexity ----------------
__global__ __launch_bounds__(256) void k_final(const float* __restrict__ varq,
                                               float* __restrict__ out, int out_size) {
    __shared__ float sh[256];
    float s = 0.f;
    for (int k = threadIdx.x; k < KC; k += 256) {
        float a = g_colsum[k] * (1.0f / (float)NR);
        s += a * logf(a + 1e-7f);
    }
    sh[threadIdx.x] = s;
    __syncthreads();
    for (int t = 128; t; t >>= 1) {
        if (threadIdx.x < t) sh[threadIdx.x] += sh[threadIdx.x + t];
        __syncthreads();
    }
    if (threadIdx.x == 0) {
        float w = 0.5f / fmaxf(varq[0], 1e-10f);
        float loss = g_scal[0] / (float)BSZ + w * g_scal[1] / (float)BSZ;
        float perp = expf(-sh[0]);
        if (out_size >= NR * DD + 2) {
            out[(size_t)NR * DD]     = loss;
            out[(size_t)NR * DD + 1] = perp;
        }
    }
}

// ---------------- launch ----------------
extern "C" void kernel_launch(void* const* d_in, const int* in_sizes, int n_in,
                              void* d_out, int out_size) {
    const float *Z = 0, *varq = 0, *CB = 0;
    for (int i = 0; i < n_in; i++) {
        if (in_sizes[i] == 1)            varq = (const float*)d_in[i];
        else if (in_sizes[i] == NR * DD) Z    = (const float*)d_in[i];
        else if (in_sizes[i] == KC * DD) CB   = (const float*)d_in[i];
    }
    float* out = (float*)d_out;

    k_zero<<<(KC + 255) / 256, 256>>>();
    k_sumsq<<<((NR + KC) * 32 + 255) / 256, 256>>>(Z, CB);
    k_gemm_logits<<<dim3(KC / 128, NR / 128), 128>>>(Z, CB, varq);
    k_mega<<<NR, 256>>>(Z, CB, out);
    k_final<<<1, 256>>>(varq, out, out_size);
}

// round 11
// speedup vs baseline: 1.6435x; 1.6435x over previous
#include <cuda_runtime.h>
#include <math.h>
#include <stdint.h>

// Problem dims (fixed by the dataset)
#define NR 4096           // bs*seq
#define KC 8192           // codebook size
#define DD 512            // feature dim
#define BSZ 8
#define TOT (NR * KC)

// ---------------- scratch (static __device__, allocation-free) ----------------
__device__ float g_logits[(size_t)NR * KC];   // 134 MB
__device__ float g_zz[NR];
__device__ float g_cc[KC];
__device__ float g_colsum[KC];
__device__ float g_scal[2];  // [0] = sum(p*logp), [1] = sum(diff^2)

// ---------------- zero accumulators (graph replays!) ----------------
__global__ void k_zero() {
    int i = blockIdx.x * blockDim.x + threadIdx.x;
    if (i < KC) g_colsum[i] = 0.f;
    if (i < 2)  g_scal[i]   = 0.f;
}

// ---------------- row squared norms ----------------
__global__ void k_sumsq(const float* __restrict__ Z, const float* __restrict__ CB) {
    int warp = (blockIdx.x * blockDim.x + threadIdx.x) >> 5;
    int lane = threadIdx.x & 31;
    if (warp >= NR + KC) return;
    const float* p = (warp < NR) ? (Z + (size_t)warp * DD)
                                 : (CB + (size_t)(warp - NR) * DD);
    float s = 0.f;
    #pragma unroll 4
    for (int i = lane; i < DD; i += 32) { float v = p[i]; s += v * v; }
    #pragma unroll
    for (int o = 16; o; o >>= 1) s += __shfl_xor_sync(0xffffffffu, s, o);
    if (lane == 0) { if (warp < NR) g_zz[warp] = s; else g_cc[warp - NR] = s; }
}

// ---------------- Threefry-2x32 gumbel (partitionable), pure fn of index ------
// counter (0, i), key (0, 42); 32-bit output = x0 ^ x1.
// uniform = bitcast(0x3f800000 | bits>>9) - 1
// gumbel = -log(-log(u+1e-10)+1e-10). Range: g in [-3.14, +15.95] exactly.
__device__ __forceinline__ float gumbel_of(unsigned i) {
    unsigned x0 = 0u, x1 = i;
    const unsigned k0 = 0u, k1 = 42u, k2 = 0x1BD11BDAu ^ k0 ^ k1;
    x0 += k0; x1 += k1;
#define TFR(r) { x0 += x1; x1 = __funnelshift_l(x1, x1, r); x1 ^= x0; }
    TFR(13) TFR(15) TFR(26) TFR(6)   x0 += k1; x1 += k2 + 1u;
    TFR(17) TFR(29) TFR(16) TFR(24)  x0 += k2; x1 += k0 + 2u;
    TFR(13) TFR(15) TFR(26) TFR(6)   x0 += k0; x1 += k1 + 3u;
    TFR(17) TFR(29) TFR(16) TFR(24)  x0 += k1; x1 += k2 + 4u;
    TFR(13) TFR(15) TFR(26) TFR(6)   x0 += k2; x1 += k0 + 5u;
#undef TFR
    unsigned bits = x0 ^ x1;
    float u = __uint_as_float(0x3f800000u | (bits >> 9)) - 1.0f;
    float x = u - 1.0f;                       // exact (Sterbenz) for u in [0.5,1]
    float pl = 1.f + x * (-0.5f + x * (0.33333334f + x * (-0.25f +
               x * (0.2f + x * (-0.16666667f + x * 0.14285715f)))));
    float ts = -x * pl;                       // accurate -ln(u), u near 1
    float tm = -__logf(u + 1e-10f);
    float t = (u > 0.9f) ? ts : tm;
    return -__logf(t + 1e-10f);
}

// ---------------- GEMM1: logits[n,k] = w*(2*Z.C^T - zz - cc) ----------------
// 128x128x16 tile, 256 threads, 8x8 micro-tile, double-buffered (R7-proven
// skeleton) with z-order warp mapping: conflict-free LDS on both operands.
#define BM1 128
#define BN1 128
#define BK1 16
#define LDT (BM1 + 8)
__global__ __launch_bounds__(256) void k_gemm_logits(
    const float* __restrict__ Z, const float* __restrict__ CB,
    const float* __restrict__ varq) {
    __shared__ float As[2][BK1][LDT];
    __shared__ float Bs[2][BK1][LDT];
    const int tid = threadIdx.x;
    const int lane = tid & 31, warp = tid >> 5;
    const int rowT = lane >> 2, colT = lane & 3;   // 8x4 lanes in warp
    const int warpRow = warp & 1, warpCol = warp >> 1;  // 2x4 warps
    const int aOff = warpRow * 64 + rowT * 8;      // row offset of 8-row strip
    const int bOff = warpCol * 32 + colT * 8;      // col offset of 8-col strip
    const int rowBase = blockIdx.y * BM1, colBase = blockIdx.x * BN1;
    const int lr = tid >> 2;     // 0..63 loader row
    const int lc = tid & 3;      // 0..3

    const float* Ap = Z  + (size_t)(rowBase + lr) * DD + lc * 4;
    const float* Bp = CB + (size_t)(colBase + lr) * DD + lc * 4;

    float4 va0 = *(const float4*)(Ap);
    float4 va1 = *(const float4*)(Ap + 64 * DD);
    float4 vb0 = *(const float4*)(Bp);
    float4 vb1 = *(const float4*)(Bp + 64 * DD);

    As[0][lc*4+0][lr]    = va0.x; As[0][lc*4+1][lr]    = va0.y;
    As[0][lc*4+2][lr]    = va0.z; As[0][lc*4+3][lr]    = va0.w;
    As[0][lc*4+0][lr+64] = va1.x; As[0][lc*4+1][lr+64] = va1.y;
    As[0][lc*4+2][lr+64] = va1.z; As[0][lc*4+3][lr+64] = va1.w;
    Bs[0][lc*4+0][lr]    = vb0.x; Bs[0][lc*4+1][lr]    = vb0.y;
    Bs[0][lc*4+2][lr]    = vb0.z; Bs[0][lc*4+3][lr]    = vb0.w;
    Bs[0][lc*4+0][lr+64] = vb1.x; Bs[0][lc*4+1][lr+64] = vb1.y;
    Bs[0][lc*4+2][lr+64] = vb1.z; Bs[0][lc*4+3][lr+64] = vb1.w;
    __syncthreads();

    float acc[8][8];
    #pragma unroll
    for (int i = 0; i < 8; i++)
        #pragma unroll
        for (int j = 0; j < 8; j++) acc[i][j] = 0.f;

    const int NIT = DD / BK1;   // 32
    for (int kk = 0; kk < NIT; kk++) {
        const int cur = kk & 1, nxt = cur ^ 1;
        if (kk + 1 < NIT) {
            const float* Ap2 = Ap + (kk + 1) * BK1;
            const float* Bp2 = Bp + (kk + 1) * BK1;
            va0 = *(const float4*)(Ap2);
            va1 = *(const float4*)(Ap2 + 64 * DD);
            vb0 = *(const float4*)(Bp2);
            vb1 = *(const float4*)(Bp2 + 64 * DD);
        }
        #pragma unroll
        for (int p = 0; p < BK1; p++) {
            float a[8], b[8];
            *(float4*)(a)     = *(const float4*)&As[cur][p][aOff];
            *(float4*)(a + 4) = *(const float4*)&As[cur][p][aOff + 4];
            *(float4*)(b)     = *(const float4*)&Bs[cur][p][bOff];
            *(float4*)(b + 4) = *(const float4*)&Bs[cur][p][bOff + 4];
            #pragma unroll
            for (int i = 0; i < 8; i++)
                #pragma unroll
                for (int j = 0; j < 8; j++) acc[i][j] += a[i] * b[j];
        }
        if (kk + 1 < NIT) {
            As[nxt][lc*4+0][lr]    = va0.x; As[nxt][lc*4+1][lr]    = va0.y;
            As[nxt][lc*4+2][lr]    = va0.z; As[nxt][lc*4+3][lr]    = va0.w;
            As[nxt][lc*4+0][lr+64] = va1.x; As[nxt][lc*4+1][lr+64] = va1.y;
            As[nxt][lc*4+2][lr+64] = va1.z; As[nxt][lc*4+3][lr+64] = va1.w;
            Bs[nxt][lc*4+0][lr]    = vb0.x; Bs[nxt][lc*4+1][lr]    = vb0.y;
            Bs[nxt][lc*4+2][lr]    = vb0.z; Bs[nxt][lc*4+3][lr]    = vb0.w;
            Bs[nxt][lc*4+0][lr+64] = vb1.x; Bs[nxt][lc*4+1][lr+64] = vb1.y;
            Bs[nxt][lc*4+2][lr+64] = vb1.z; Bs[nxt][lc*4+3][lr+64] = vb1.w;
        }
        __syncthreads();
    }

    const float w = 0.5f / fmaxf(varq[0], 1e-10f);
    float cc[8];
    #pragma unroll
    for (int q = 0; q < 8; q++) cc[q] = g_cc[colBase + bOff + q];
    #pragma unroll
    for (int i = 0; i < 8; i++) {
        int n = rowBase + aOff + i;
        float zzn = g_zz[n];
        float* dst = g_logits + (size_t)n * KC + colBase + bOff;
        float4 v0, v1;
        v0.x = w * (2.f * acc[i][0] - zzn - cc[0]);
        v0.y = w * (2.f * acc[i][1] - zzn - cc[1]);
        v0.z = w * (2.f * acc[i][2] - zzn - cc[2]);
        v0.w = w * (2.f * acc[i][3] - zzn - cc[3]);
        v1.x = w * (2.f * acc[i][4] - zzn - cc[4]);
        v1.y = w * (2.f * acc[i][5] - zzn - cc[5]);
        v1.z = w * (2.f * acc[i][6] - zzn - cc[6]);
        v1.w = w * (2.f * acc[i][7] - zzn - cc[7]);
        *(float4*)(dst)     = v0;
        *(float4*)(dst + 4) = v1;
    }
}

// ---------------- mega kernel: stats + colsum + sparse gumbel decode + diff ----
// Phase 1: (m1,Z1,T1) over logits only (exact kld_discrete).
// Phase 2: colsum atomics for p>1e-9; Threefry ONLY for l > m1-28.5 (provably
//          covers all y >= m2-18.8 since gumbel in [-3.14, 15.95]).
// Phase 3: m2/Z2 over candidates; z_dec = sum E_k*CB[k]; fused diff^2.
#define CCAP 256
__global__ __launch_bounds__(256) void k_mega(const float* __restrict__ Z,
                                              const float* __restrict__ CB,
                                              float* __restrict__ out) {
    const int n = blockIdx.x;
    const float* __restrict__ lrow = g_logits + (size_t)n * KC;
    const unsigned ibase = (unsigned)n * KC;
    const int t = threadIdx.x;

    float m1 = -1e30f, Z1 = 0.f, T1 = 0.f;
    for (int k = t * 4; k < KC; k += 1024) {
        float4 l4 = *(const float4*)(lrow + k);
        #pragma unroll
        for (int q = 0; q < 4; q++) {
            float l = (q == 0) ? l4.x : (q == 1) ? l4.y : (q == 2) ? l4.z : l4.w;
            if (l > m1) {
                float d = m1 - l;
                float sc = __expf(d);
                T1 = sc * (T1 + d * Z1);
                Z1 *= sc;
                m1 = l;
            }
            float e = __expf(l - m1);
            Z1 += e; T1 += e * (l - m1);
        }
    }
    __shared__ float sm[256], sz[256], st[256];
    __shared__ float s_fin[6];
    __shared__ int ccnt;
    __shared__ int   cidx[CCAP];
    __shared__ float cy[CCAP];
    sm[t] = m1; sz[t] = Z1; st[t] = T1;
    __syncthreads();
    for (int s = 128; s; s >>= 1) {
        if (t < s) {
            int o = t + s;
            float M = fmaxf(sm[t], sm[o]);
            float da = sm[t] - M, db = sm[o] - M;
            float ea = __expf(da), eb = __expf(db);
            st[t] = ea * (st[t] + da * sz[t]) + eb * (st[o] + db * sz[o]);
            sz[t] = ea * sz[t] + eb * sz[o];
            sm[t] = M;
        }
        __syncthreads();
    }
    if (t == 0) {
        float M = sm[0], Zz = sz[0], T = st[0];
        atomicAdd(&g_scal[0], T / Zz - logf(Zz));   // exact row sum p*logp
        s_fin[0] = M;
        s_fin[1] = 1.f / Zz;
        s_fin[2] = M + logf(Zz) - 20.723f;          // p > 1e-9 cut
        s_fin[3] = M - 28.5f;                       // candidate cut
        ccnt = 0;
    }
    __syncthreads();
    const float m1v = s_fin[0], iZ1 = s_fin[1], lpc = s_fin[2], ccut = s_fin[3];

    for (int k = t * 4; k < KC; k += 1024) {
        float4 l4 = *(const float4*)(lrow + k);
        #pragma unroll
        for (int q = 0; q < 4; q++) {
            float l = (q == 0) ? l4.x : (q == 1) ? l4.y : (q == 2) ? l4.z : l4.w;
            if (l > lpc)
                atomicAdd(&g_colsum[k + q], __expf(l - m1v) * iZ1);
            if (l > ccut) {
                int s = atomicAdd(&ccnt, 1);
                if (s < CCAP) {
                    cidx[s] = k + q;
                    cy[s]   = 2.0f * (l + gumbel_of(ibase + k + q));
                }
            }
        }
    }
    __syncthreads();
    const int cnt = min(ccnt, CCAP);

    // m2 = max over candidates
    float lm = -1e30f;
    for (int j = t; j < cnt; j += 256) lm = fmaxf(lm, cy[j]);
    sm[t] = lm;
    __syncthreads();
    for (int s = 128; s; s >>= 1) {
        if (t < s) sm[t] = fmaxf(sm[t], sm[t + s]);
        __syncthreads();
    }
    if (t == 0) s_fin[4] = sm[0];
    __syncthreads();
    const float m2v = s_fin[4];

    // Z2 over candidates
    float lz = 0.f;
    for (int j = t; j < cnt; j += 256) lz += __expf(cy[j] - m2v);
    sm[t] = lz;
    __syncthreads();
    for (int s = 128; s; s >>= 1) {
        if (t < s) sm[t] += sm[t + s];
        __syncthreads();
    }
    if (t == 0) s_fin[5] = 1.f / sm[0];
    __syncthreads();
    const float iZ2 = s_fin[5];
    for (int j = t; j < cnt; j += 256) cy[j] = __expf(cy[j] - m2v) * iZ2;
    __syncthreads();

    // decode: z_dec[n][:] = sum_j E_j * CB[cidx_j][:]; fused diff^2
    const int c0 = t * 2;
    float a0 = 0.f, a1 = 0.f;
    for (int j = 0; j < cnt; j++) {
        float e = cy[j];
        float2 cb = *(const float2*)(CB + (size_t)cidx[j] * DD + c0);
        a0 += e * cb.x;
        a1 += e * cb.y;
    }
    out[(size_t)n * DD + c0]     = a0;
    out[(size_t)n * DD + c0 + 1] = a1;
    float2 z2 = *(const float2*)(Z + (size_t)n * DD + c0);
    float d0 = z2.x - a0, d1 = z2.y - a1;
    sm[t] = d0 * d0 + d1 * d1;
    __syncthreads();
    for (int s = 128; s; s >>= 1) {
        if (t < s) sm[t] += sm[t + s];
        __syncthreads();
    }
    if (t == 0) atomicAdd(&g_scal[1], sm[0]);
}

// ---------------- finalize loss + perplexity ----------------
__global__ __launch_bounds__(256) void k_final(const float* __restrict__ varq,
                                               float* __restrict__ out, int out_size) {
    __shared__ float sh[256];
    float s = 0.f;
    for (int k = threadIdx.x; k < KC; k += 256) {
        float a = g_colsum[k] * (1.0f / (float)NR);
        s += a * logf(a + 1e-7f);
    }
    sh[threadIdx.x] = s;
    __syncthreads();
    for (int t = 128; t; t >>= 1) {
        if (threadIdx.x < t) sh[threadIdx.x] += sh[threadIdx.x + t];
        __syncthreads();
    }
    if (threadIdx.x == 0) {
        float w = 0.5f / fmaxf(varq[0], 1e-10f);
        float loss = g_scal[0] / (float)BSZ + w * g_scal[1] / (float)BSZ;
        float perp = expf(-sh[0]);
        if (out_size >= NR * DD + 2) {
            out[(size_t)NR * DD]     = loss;
            out[(size_t)NR * DD + 1] = perp;
        }
    }
}

// ---------------- launch ----------------
extern "C" void kernel_launch(void* const* d_in, const int* in_sizes, int n_in,
                              void* d_out, int out_size) {
    const float *Z = 0, *varq = 0, *CB = 0;
    for (int i = 0; i < n_in; i++) {
        if (in_sizes[i] == 1)            varq = (const float*)d_in[i];
        else if (in_sizes[i] == NR * DD) Z    = (const float*)d_in[i];
        else if (in_sizes[i] == KC * DD) CB   = (const float*)d_in[i];
    }
    float* out = (float*)d_out;

    k_zero<<<(KC + 255) / 256, 256>>>();
    k_sumsq<<<((NR + KC) * 32 + 255) / 256, 256>>>(Z, CB);
    k_gemm_logits<<<dim3(KC / BN1, NR / BM1), 256>>>(Z, CB, varq);
    k_mega<<<NR, 256>>>(Z, CB, out);
    k_final<<<1, 256>>>(varq, out, out_size);
}